// round 7
// baseline (speedup 1.0000x reference)
#include <cuda_runtime.h>
#include <math.h>

#define BB 32
#define CC 256
#define HWD 96
#define ROW4 (HWD/4)         // 24 float4 per row
#define PLANE (HWD*HWD)      // 9216
#define NPLANES (BB*CC)      // 8192
#define KK 9
#define W2ROWS (CC*KK)       // 2304
#define CHUNK_B 4            // batches per chunk (37.7 MB of x -> L2 resident)
#define NCHUNK (BB/CHUNK_B)  // 8

// scratch (no allocations allowed)
__device__ float g_pooled[BB*CC];
__device__ float g_wdyn[BB*CC*KK];

// ---------------------------------------------------------------------------
// Kernel 1: global average pool, chunked. 1 block = 1 plane of the chunk.
// Default-cached loads: x stays resident in L2 for the conv of this chunk.
// ---------------------------------------------------------------------------
__global__ __launch_bounds__(256) void pool_kernel(const float* __restrict__ x,
                                                   int b0) {
    const int plane = b0 * CC + blockIdx.x;
    const float4* __restrict__ xp =
        reinterpret_cast<const float4*>(x + (size_t)plane * PLANE);
    float sum = 0.f;
#pragma unroll
    for (int it = 0; it < 9; ++it) {
        float4 v = xp[threadIdx.x + it * 256];
        sum += (v.x + v.y) + (v.z + v.w);
    }
#pragma unroll
    for (int o = 16; o > 0; o >>= 1)
        sum += __shfl_xor_sync(0xffffffffu, sum, o);
    __shared__ float ws[8];
    const int lane = threadIdx.x & 31, wid = threadIdx.x >> 5;
    if (lane == 0) ws[wid] = sum;
    __syncthreads();
    if (threadIdx.x == 0) {
        float t = 0.f;
#pragma unroll
        for (int i = 0; i < 8; ++i) t += ws[i];
        g_pooled[plane] = t * (1.0f / (float)PLANE);
    }
}

// ---------------------------------------------------------------------------
// Kernel 2: dynamic net, chunked. grid = (9, CHUNK_B).
// ---------------------------------------------------------------------------
__global__ __launch_bounds__(256) void dyn_kernel(const float* __restrict__ w1,
                                                  const float* __restrict__ b1,
                                                  const float* __restrict__ w2,
                                                  const float* __restrict__ b2,
                                                  int b0) {
    const int b  = b0 + blockIdx.y;
    const int r0 = blockIdx.x;
    const int c  = threadIdx.x;
    __shared__ float ps[CC];
    __shared__ float hs[CC];
    ps[c] = g_pooled[b * CC + c];
    __syncthreads();

    {
        float acc = b1[c];
        const float4* __restrict__ wr =
            reinterpret_cast<const float4*>(w1 + (size_t)c * CC);
        const float4* __restrict__ pv = reinterpret_cast<const float4*>(ps);
#pragma unroll 8
        for (int k = 0; k < CC / 4; ++k) {
            float4 a = pv[k];
            float4 w = wr[k];
            acc += a.x * w.x + a.y * w.y + a.z * w.z + a.w * w.w;
        }
        hs[c] = 0.5f * acc * (1.0f + erff(acc * 0.70710678118654752f));
    }
    __syncthreads();

    const int r = r0 * 256 + c;
    float acc = b2[r];
    const float4* __restrict__ wr =
        reinterpret_cast<const float4*>(w2 + (size_t)r * CC);
    const float4* __restrict__ hv = reinterpret_cast<const float4*>(hs);
#pragma unroll 8
    for (int k = 0; k < CC / 4; ++k) {
        float4 a = hv[k];
        float4 w = wr[k];
        acc += a.x * w.x + a.y * w.y + a.z * w.z + a.w * w.w;
    }
    g_wdyn[(size_t)b * W2ROWS + r] = acc;
}

// ---------------------------------------------------------------------------
// Kernel 3: conv, chunked. Reads x from L2 (just pulled in by pool_kernel),
// streams output with __stcs. Block = 1 plane, 288 threads = 24 strips x 12
// row-chunks; each thread slides a register window over 8 output rows.
// ---------------------------------------------------------------------------
struct Row6 { float4 c; float l, r; };

__device__ __forceinline__ Row6 load_row_s(const float* __restrict__ s,
                                           int y, int xb, int x4) {
    Row6 o;
    const float* rp = s + y * HWD;
    o.c = *reinterpret_cast<const float4*>(rp + xb);
    // horizontal reflect: left of col0 = col1 (c.y); right of col95 = col94 (c.z)
    o.l = (x4 == 0)        ? o.c.y : rp[xb - 1];
    o.r = (x4 == ROW4 - 1) ? o.c.z : rp[xb + 4];
    return o;
}

__device__ __forceinline__ void row_fma(float4& acc, const Row6& rr,
                                        float wl, float wc, float wr) {
    acc.x += rr.l   * wl + rr.c.x * wc + rr.c.y * wr;
    acc.y += rr.c.x * wl + rr.c.y * wc + rr.c.z * wr;
    acc.z += rr.c.y * wl + rr.c.z * wc + rr.c.w * wr;
    acc.w += rr.c.z * wl + rr.c.w * wc + rr.r   * wr;
}

__global__ __launch_bounds__(288) void conv_kernel(const float* __restrict__ x,
                                                   float* __restrict__ out,
                                                   int b0) {
    const int plane = b0 * CC + blockIdx.x;
    __shared__ float s[PLANE];
    const int tid = threadIdx.x;

    const float4* __restrict__ xp =
        reinterpret_cast<const float4*>(x + (size_t)plane * PLANE);
    float4* sp = reinterpret_cast<float4*>(s);
#pragma unroll
    for (int it = 0; it < 8; ++it)                  // 2304/288 = 8
        sp[tid + it * 288] = xp[tid + it * 288];    // L2 hits (pool warmed it)

    float w[KK];
    const float* __restrict__ wd = g_wdyn + (size_t)plane * KK;
#pragma unroll
    for (int i = 0; i < KK; ++i) w[i] = wd[i];
    __syncthreads();

    const int x4 = tid % ROW4;      // strip 0..23
    const int cy = tid / ROW4;      // chunk 0..11
    const int y0 = cy * 8;
    const int xb = x4 * 4;

    // vertical reflect: row -1 -> 1 (only applies when cy==0)
    Row6 prev = load_row_s(s, (cy == 0) ? 1 : (y0 - 1), xb, x4);
    Row6 cur  = load_row_s(s, y0, xb, x4);

    float4* __restrict__ o4 =
        reinterpret_cast<float4*>(out + (size_t)plane * PLANE);

#pragma unroll
    for (int i = 0; i < 8; ++i) {
        const int y  = y0 + i;
        const int yn = (y == HWD - 1) ? HWD - 2 : y + 1;  // reflect 96 -> 94
        Row6 nxt = load_row_s(s, yn, xb, x4);
        float4 acc = make_float4(0.f, 0.f, 0.f, 0.f);
        row_fma(acc, prev, w[0], w[1], w[2]);
        row_fma(acc, cur,  w[3], w[4], w[5]);
        row_fma(acc, nxt,  w[6], w[7], w[8]);
        __stcs(&o4[y * ROW4 + x4], acc);                  // evict-first store
        prev = cur; cur = nxt;
    }
}

// ---------------------------------------------------------------------------
extern "C" void kernel_launch(void* const* d_in, const int* in_sizes, int n_in,
                              void* d_out, int out_size) {
    const float* x  = (const float*)d_in[0];   // (32,256,96,96)
    const float* w1 = (const float*)d_in[1];   // (256,256)
    const float* b1 = (const float*)d_in[2];   // (256,)
    const float* w2 = (const float*)d_in[3];   // (2304,256)
    const float* b2 = (const float*)d_in[4];   // (2304,)
    float* out = (float*)d_out;

    for (int c = 0; c < NCHUNK; ++c) {
        const int b0 = c * CHUNK_B;
        pool_kernel<<<CHUNK_B * CC, 256>>>(x, b0);
        dyn_kernel<<<dim3(KK, CHUNK_B), 256>>>(w1, b1, w2, b2, b0);
        conv_kernel<<<CHUNK_B * CC, 288>>>(x, out, b0);
    }
}

// round 8
// speedup vs baseline: 1.9409x; 1.9409x over previous
#include <cuda_runtime.h>
#include <math.h>
#include <stdint.h>

#define BB 32
#define CC 256
#define HWD 96
#define ROW4 (HWD/4)         // 24 float4 per row
#define PLANE (HWD*HWD)      // 9216
#define PLANE_BYTES (PLANE*4)
#define NPLANES (BB*CC)      // 8192
#define KK 9
#define W2ROWS (CC*KK)       // 2304

// scratch (no allocations allowed)
__device__ float g_pooled[BB*CC];
__device__ float g_wdyn[BB*CC*KK];

// ---------------------------------------------------------------------------
// Kernel 1: global average pool per (b,c) plane. 1 block = 1 plane.
// ~84% DRAM roofline measured.
// ---------------------------------------------------------------------------
__global__ __launch_bounds__(256) void pool_kernel(const float* __restrict__ x) {
    const int plane = blockIdx.x;
    const float4* __restrict__ xp =
        reinterpret_cast<const float4*>(x + (size_t)plane * PLANE);
    float sum = 0.f;
#pragma unroll
    for (int it = 0; it < 9; ++it) {
        float4 v = xp[threadIdx.x + it * 256];
        sum += (v.x + v.y) + (v.z + v.w);
    }
#pragma unroll
    for (int o = 16; o > 0; o >>= 1)
        sum += __shfl_xor_sync(0xffffffffu, sum, o);
    __shared__ float ws[8];
    const int lane = threadIdx.x & 31, wid = threadIdx.x >> 5;
    if (lane == 0) ws[wid] = sum;
    __syncthreads();
    if (threadIdx.x == 0) {
        float t = 0.f;
#pragma unroll
        for (int i = 0; i < 8; ++i) t += ws[i];
        g_pooled[plane] = t * (1.0f / (float)PLANE);
    }
}

// ---------------------------------------------------------------------------
// Kernel 2: dynamic net. grid = (9, 32).
// ---------------------------------------------------------------------------
__global__ __launch_bounds__(256) void dyn_kernel(const float* __restrict__ w1,
                                                  const float* __restrict__ b1,
                                                  const float* __restrict__ w2,
                                                  const float* __restrict__ b2) {
    const int b  = blockIdx.y;
    const int r0 = blockIdx.x;
    const int c  = threadIdx.x;
    __shared__ float ps[CC];
    __shared__ float hs[CC];
    ps[c] = g_pooled[b * CC + c];
    __syncthreads();

    {
        float acc = b1[c];
        const float4* __restrict__ wr =
            reinterpret_cast<const float4*>(w1 + (size_t)c * CC);
        const float4* __restrict__ pv = reinterpret_cast<const float4*>(ps);
#pragma unroll 8
        for (int k = 0; k < CC / 4; ++k) {
            float4 a = pv[k];
            float4 w = wr[k];
            acc += a.x * w.x + a.y * w.y + a.z * w.z + a.w * w.w;
        }
        hs[c] = 0.5f * acc * (1.0f + erff(acc * 0.70710678118654752f));
    }
    __syncthreads();

    const int r = r0 * 256 + c;
    float acc = b2[r];
    const float4* __restrict__ wr =
        reinterpret_cast<const float4*>(w2 + (size_t)r * CC);
    const float4* __restrict__ hv = reinterpret_cast<const float4*>(hs);
#pragma unroll 8
    for (int k = 0; k < CC / 4; ++k) {
        float4 a = hv[k];
        float4 w = wr[k];
        acc += a.x * w.x + a.y * w.y + a.z * w.z + a.w * w.w;
    }
    g_wdyn[(size_t)b * W2ROWS + r] = acc;
}

// ---------------------------------------------------------------------------
// Kernel 3 v5: TMA bulk load of the plane into smem (one cp.async.bulk per
// block, mbarrier complete_tx) + register-sliding row window + STG.128.
// Block = 1 plane, 288 threads = 24 strips x 12 row-chunks of 8 rows.
// Reverse plane order for L2 tail reuse from pool.
// ---------------------------------------------------------------------------
struct Row6 { float4 c; float l, r; };

__device__ __forceinline__ Row6 load_row_s(const float* __restrict__ s,
                                           int y, int xb, int x4) {
    Row6 o;
    const float* rp = s + y * HWD;
    o.c = *reinterpret_cast<const float4*>(rp + xb);
    o.l = (x4 == 0)        ? o.c.y : rp[xb - 1];      // reflect col -1 -> 1
    o.r = (x4 == ROW4 - 1) ? o.c.z : rp[xb + 4];      // reflect col 96 -> 94
    return o;
}

__device__ __forceinline__ void row_fma(float4& acc, const Row6& rr,
                                        float wl, float wc, float wr) {
    acc.x += rr.l   * wl + rr.c.x * wc + rr.c.y * wr;
    acc.y += rr.c.x * wl + rr.c.y * wc + rr.c.z * wr;
    acc.z += rr.c.y * wl + rr.c.z * wc + rr.c.w * wr;
    acc.w += rr.c.z * wl + rr.c.w * wc + rr.r   * wr;
}

__global__ __launch_bounds__(288) void conv_kernel(const float* __restrict__ x,
                                                   float* __restrict__ out) {
    const int plane = (NPLANES - 1) - blockIdx.x;     // reverse: L2 tail reuse
    __shared__ __align__(16) float s[PLANE];
    __shared__ __align__(8) uint64_t mbar;
    const int tid = threadIdx.x;

    uint32_t s_u32, mbar_u32;
    asm("{ .reg .u64 t; cvta.to.shared.u64 t, %1; cvt.u32.u64 %0, t; }"
        : "=r"(s_u32) : "l"((const void*)s));
    asm("{ .reg .u64 t; cvta.to.shared.u64 t, %1; cvt.u32.u64 %0, t; }"
        : "=r"(mbar_u32) : "l"((const void*)&mbar));

    if (tid == 0) {
        asm volatile("mbarrier.init.shared.b64 [%0], 1;" :: "r"(mbar_u32) : "memory");
        asm volatile("fence.proxy.async.shared::cta;" ::: "memory");
        asm volatile("mbarrier.arrive.expect_tx.shared.b64 _, [%0], %1;"
                     :: "r"(mbar_u32), "r"((unsigned)PLANE_BYTES) : "memory");
        asm volatile(
            "cp.async.bulk.shared::cta.global.mbarrier::complete_tx::bytes "
            "[%0], [%1], %2, [%3];"
            :: "r"(s_u32), "l"(x + (size_t)plane * PLANE),
               "r"((unsigned)PLANE_BYTES), "r"(mbar_u32)
            : "memory");
    }

    // overlap: fetch the 9 dynamic weights while the bulk copy flies
    float w[KK];
    const float* __restrict__ wd = g_wdyn + (size_t)plane * KK;
#pragma unroll
    for (int i = 0; i < KK; ++i) w[i] = wd[i];

    __syncthreads();   // mbar.init visible to all before anyone waits
    {
        unsigned done = 0;
        while (!done) {
            asm volatile(
                "{\n .reg .pred p;\n"
                " mbarrier.try_wait.parity.acquire.cta.shared::cta.b64 p, [%1], %2, 0x989680;\n"
                " selp.b32 %0, 1, 0, p;\n}"
                : "=r"(done) : "r"(mbar_u32), "r"(0u) : "memory");
        }
    }

    const int x4 = tid % ROW4;      // strip 0..23
    const int cy = tid / ROW4;      // chunk 0..11
    const int y0 = cy * 8;
    const int xb = x4 * 4;

    Row6 prev = load_row_s(s, (cy == 0) ? 1 : (y0 - 1), xb, x4);  // reflect -1 -> 1
    Row6 cur  = load_row_s(s, y0, xb, x4);

    float4* __restrict__ o4 =
        reinterpret_cast<float4*>(out + (size_t)plane * PLANE);

#pragma unroll
    for (int i = 0; i < 8; ++i) {
        const int y  = y0 + i;
        const int yn = (y == HWD - 1) ? HWD - 2 : y + 1;          // reflect 96 -> 94
        Row6 nxt = load_row_s(s, yn, xb, x4);
        float4 acc = make_float4(0.f, 0.f, 0.f, 0.f);
        row_fma(acc, prev, w[0], w[1], w[2]);
        row_fma(acc, cur,  w[3], w[4], w[5]);
        row_fma(acc, nxt,  w[6], w[7], w[8]);
        __stcs(&o4[y * ROW4 + x4], acc);
        prev = cur; cur = nxt;
    }
}

// ---------------------------------------------------------------------------
extern "C" void kernel_launch(void* const* d_in, const int* in_sizes, int n_in,
                              void* d_out, int out_size) {
    const float* x  = (const float*)d_in[0];   // (32,256,96,96)
    const float* w1 = (const float*)d_in[1];   // (256,256)
    const float* b1 = (const float*)d_in[2];   // (256,)
    const float* w2 = (const float*)d_in[3];   // (2304,256)
    const float* b2 = (const float*)d_in[4];   // (2304,)
    float* out = (float*)d_out;

    pool_kernel<<<NPLANES, 256>>>(x);
    dyn_kernel<<<dim3(KK, BB), 256>>>(w1, b1, w2, b2);
    conv_kernel<<<NPLANES, 288>>>(x, out);
}